// round 10
// baseline (speedup 1.0000x reference)
#include <cuda_runtime.h>
#include <cuda_bf16.h>
#include <cstdint>

// Problem constants (fixed shapes per reference)
#define NN      100000
#define EE      1600000
#define FF      256
#define HH      8
#define CC      8
#define HC      64
#define NEG_SLOPE 0.2f

// ---------------- scratch (device globals; no allocation allowed) ----------
__device__ __align__(16) float g_h[NN * HC];      // projected features [N,64]
__device__ __align__(16) float g_asrc[NN * HH];   // per-node src attention [N,8]
__device__ __align__(16) float g_adst[NN * HH];   // per-node dst attention [N,8]
__device__ __align__(16) float g_s[NN * HH];      // softmax denominators [N,8]
__device__ int g_is64;                            // edge_index dtype flag

// ---------------- helpers --------------------------------------------------
__device__ __forceinline__ float lrelu(float v) {
    return v > 0.f ? v : NEG_SLOPE * v;
}

__device__ __forceinline__ void red_add_f4(float* addr, float4 v) {
    asm volatile("red.global.add.v4.f32 [%0], {%1,%2,%3,%4};"
                 :: "l"(addr), "f"(v.x), "f"(v.y), "f"(v.z), "f"(v.w)
                 : "memory");
}

// Load (src, dst) for edge e, branching on detected dtype (uniform branch).
__device__ __forceinline__ void load_edge(const void* eiv, int is64, int E,
                                          int e, int& src, int& dst) {
    if (is64) {
        const long long* p = (const long long*)eiv;
        src = (int)p[e];
        dst = (int)p[(size_t)E + e];
    } else {
        const int* p = (const int*)eiv;
        src = p[e];
        dst = p[E + e];
    }
}

// ---------------- K0: edge_index dtype probe -------------------------------
// int64 values < 2^31 => all odd int32 words are zero (little-endian).
// int32 => odd words are random node ids; 64 zeros is impossible (p~1e-320).
__global__ void detect_kernel(const int* ei) {
    int nz = 0;
#pragma unroll
    for (int i = 0; i < 64; i++) nz |= ei[2 * i + 1];
    g_is64 = (nz == 0) ? 1 : 0;
}

// ---------------- K1: GEMM h = x @ W^T  ([N,256]x[64,256]^T -> [N,64]) -----
// 64 rows x 64 cols per block, BK=64, 256 threads, 4x4 register tile.
__global__ __launch_bounds__(256) void gemm_kernel(
    const float* __restrict__ x, const float* __restrict__ W,
    float* __restrict__ h, int n)
{
    __shared__ float sA[64][64];   // [k][row]
    __shared__ float sB[64][64];   // [k][col]

    const int tid = threadIdx.x;
    const int r0  = blockIdx.x * 64;
    const int row = tid & 63;          // also used as W col index on load
    const int kb  = (tid >> 6) * 16;   // 0,16,32,48
    const int ty  = tid >> 4;          // 0..15 (row group)
    const int tx  = tid & 15;          // 0..15 (col group)

    float acc[4][4];
#pragma unroll
    for (int i = 0; i < 4; i++)
#pragma unroll
        for (int j = 0; j < 4; j++) acc[i][j] = 0.f;

    for (int k0 = 0; k0 < FF; k0 += 64) {
        // load x tile [64 rows][64 k] -> sA[k][row]
        const int gr = r0 + row;
#pragma unroll
        for (int j = 0; j < 4; j++) {
            const int kk = kb + j * 4;
            float4 v = make_float4(0.f, 0.f, 0.f, 0.f);
            if (gr < n)
                v = *(const float4*)&x[(size_t)gr * FF + k0 + kk];
            sA[kk + 0][row] = v.x;
            sA[kk + 1][row] = v.y;
            sA[kk + 2][row] = v.z;
            sA[kk + 3][row] = v.w;
        }
        // load W tile: W[col][k] -> sB[k][col]  (W has exactly 64 rows)
#pragma unroll
        for (int j = 0; j < 4; j++) {
            const int kk = kb + j * 4;
            float4 v = *(const float4*)&W[(size_t)row * FF + k0 + kk];
            sB[kk + 0][row] = v.x;
            sB[kk + 1][row] = v.y;
            sB[kk + 2][row] = v.z;
            sB[kk + 3][row] = v.w;
        }
        __syncthreads();

#pragma unroll 16
        for (int kk = 0; kk < 64; kk++) {
            const float4 a = *(const float4*)&sA[kk][ty * 4];
            const float4 b = *(const float4*)&sB[kk][tx * 4];
            acc[0][0] += a.x * b.x; acc[0][1] += a.x * b.y; acc[0][2] += a.x * b.z; acc[0][3] += a.x * b.w;
            acc[1][0] += a.y * b.x; acc[1][1] += a.y * b.y; acc[1][2] += a.y * b.z; acc[1][3] += a.y * b.w;
            acc[2][0] += a.z * b.x; acc[2][1] += a.z * b.y; acc[2][2] += a.z * b.z; acc[2][3] += a.z * b.w;
            acc[3][0] += a.w * b.x; acc[3][1] += a.w * b.y; acc[3][2] += a.w * b.z; acc[3][3] += a.w * b.w;
        }
        __syncthreads();
    }

#pragma unroll
    for (int i = 0; i < 4; i++) {
        const int gr = r0 + ty * 4 + i;
        if (gr < n) {
            float4 v = make_float4(acc[i][0], acc[i][1], acc[i][2], acc[i][3]);
            *(float4*)&h[(size_t)gr * HC + tx * 4] = v;
        }
    }
}

// ---------------- K2: per-(node,head) attention terms + zero denominators --
__global__ void att_kernel(const float* __restrict__ h,
                           const float* __restrict__ att_src,
                           const float* __restrict__ att_dst,
                           float* __restrict__ asrc, float* __restrict__ adst,
                           float* __restrict__ s, int n)
{
    const int i = blockIdx.x * blockDim.x + threadIdx.x;
    if (i >= n * HH) return;
    const int node = i >> 3;
    const int hd   = i & 7;

    const float4 h0 = *(const float4*)&h[(size_t)node * HC + hd * 8];
    const float4 h1 = *(const float4*)&h[(size_t)node * HC + hd * 8 + 4];
    const float4 s0 = *(const float4*)&att_src[hd * 8];
    const float4 s1 = *(const float4*)&att_src[hd * 8 + 4];
    const float4 d0 = *(const float4*)&att_dst[hd * 8];
    const float4 d1 = *(const float4*)&att_dst[hd * 8 + 4];

    float as = h0.x * s0.x + h0.y * s0.y + h0.z * s0.z + h0.w * s0.w
             + h1.x * s1.x + h1.y * s1.y + h1.z * s1.z + h1.w * s1.w;
    float ad = h0.x * d0.x + h0.y * d0.y + h0.z * d0.z + h0.w * d0.w
             + h1.x * d1.x + h1.y * d1.y + h1.z * d1.z + h1.w * d1.w;

    asrc[i] = as;
    adst[i] = ad;
    s[i]    = 0.f;
}

// ---------------- K3: softmax denominators (exp without max-shift) ---------
// One thread per edge (incl. self-loops at e >= E). 2x red.v4 per edge.
__global__ void edge_sum_kernel(const void* eiv, int E, int n,
                                const float* __restrict__ asrc,
                                const float* __restrict__ adst,
                                float* __restrict__ s)
{
    const int e = blockIdx.x * blockDim.x + threadIdx.x;
    const int ET = E + n;
    if (e >= ET) return;
    const int is64 = g_is64;
    int src, dst;
    if (e < E) load_edge(eiv, is64, E, e, src, dst);
    else       src = dst = e - E;

    const float4 a0 = *(const float4*)&asrc[(size_t)src * HH];
    const float4 a1 = *(const float4*)&asrc[(size_t)src * HH + 4];
    const float4 b0 = *(const float4*)&adst[(size_t)dst * HH];
    const float4 b1 = *(const float4*)&adst[(size_t)dst * HH + 4];

    float4 p0, p1;
    p0.x = __expf(lrelu(a0.x + b0.x));
    p0.y = __expf(lrelu(a0.y + b0.y));
    p0.z = __expf(lrelu(a0.z + b0.z));
    p0.w = __expf(lrelu(a0.w + b0.w));
    p1.x = __expf(lrelu(a1.x + b1.x));
    p1.y = __expf(lrelu(a1.y + b1.y));
    p1.z = __expf(lrelu(a1.z + b1.z));
    p1.w = __expf(lrelu(a1.w + b1.w));

    red_add_f4(&s[(size_t)dst * HH], p0);
    red_add_f4(&s[(size_t)dst * HH + 4], p1);
}

// ---------------- K4: weighted message aggregation -------------------------
// 16 threads per edge; each thread handles one float4 of the 64-wide feature.
// Even/odd thread pairs share a head: even computes alpha, odd shuffles it.
// NOTE: ET*16 is divisible by 256 for these shapes -> no partial warps, so
// the full-mask shfl after the early return is safe.
__global__ void aggregate_kernel(const void* eiv, int E, int n,
                                 const float* __restrict__ asrc,
                                 const float* __restrict__ adst,
                                 const float* __restrict__ s,
                                 const float* __restrict__ h,
                                 float* __restrict__ out)
{
    const int gid = blockIdx.x * blockDim.x + threadIdx.x;
    const int e = gid >> 4;
    const int q = gid & 15;
    const int ET = E + n;
    if (e >= ET) return;
    const int is64 = g_is64;
    int src, dst;
    if (e < E) load_edge(eiv, is64, E, e, src, dst);
    else       src = dst = e - E;

    const int hd = q >> 1;  // head index (shared by thread pair q, q^1)
    float alpha;
    if ((q & 1) == 0) {
        const float ev = lrelu(asrc[(size_t)src * HH + hd] + adst[(size_t)dst * HH + hd]);
        alpha = __expf(ev) / (s[(size_t)dst * HH + hd] + 1e-16f);
    }
    alpha = __shfl_sync(0xFFFFFFFFu, alpha, threadIdx.x & ~1, 32);

    const float4 hv = *(const float4*)&h[(size_t)src * HC + q * 4];
    float4 m = make_float4(hv.x * alpha, hv.y * alpha, hv.z * alpha, hv.w * alpha);
    red_add_f4(&out[(size_t)dst * HC + q * 4], m);
}

// ---------------- K5: bias + log_softmax over 64 columns (warp per node) ---
__global__ void logsoftmax_kernel(float* __restrict__ out,
                                  const float* __restrict__ bias, int n)
{
    const int warp = (blockIdx.x * blockDim.x + threadIdx.x) >> 5;
    const int lane = threadIdx.x & 31;
    if (warp >= n) return;

    float v0 = out[(size_t)warp * HC + lane]      + bias[lane];
    float v1 = out[(size_t)warp * HC + 32 + lane] + bias[32 + lane];

    float m = fmaxf(v0, v1);
#pragma unroll
    for (int o = 16; o > 0; o >>= 1)
        m = fmaxf(m, __shfl_xor_sync(0xFFFFFFFFu, m, o));

    float sum = __expf(v0 - m) + __expf(v1 - m);
#pragma unroll
    for (int o = 16; o > 0; o >>= 1)
        sum += __shfl_xor_sync(0xFFFFFFFFu, sum, o);

    const float lse = m + __logf(sum);
    out[(size_t)warp * HC + lane]      = v0 - lse;
    out[(size_t)warp * HC + 32 + lane] = v1 - lse;
}

// ---------------- launch ---------------------------------------------------
extern "C" void kernel_launch(void* const* d_in, const int* in_sizes, int n_in,
                              void* d_out, int out_size)
{
    const float* x        = (const float*)d_in[0];
    const void*  ei       = d_in[1];                 // int32 OR int64, probed
    const float* W        = (const float*)d_in[2];
    const float* att_src  = (const float*)d_in[3];
    const float* att_dst  = (const float*)d_in[4];
    const float* bias     = (const float*)d_in[5];
    float*       out      = (float*)d_out;

    const int n = in_sizes[0] / FF;       // 100000
    const int E = in_sizes[1] / 2;        // 1600000
    const int ET = E + n;

    // zero the output accumulator (d_out is poisoned to 0xAA)
    cudaMemsetAsync(d_out, 0, (size_t)out_size * sizeof(float));

    // K0: probe edge_index dtype (1 thread, reads 256 bytes)
    detect_kernel<<<1, 1>>>((const int*)ei);

    // K1: GEMM
    gemm_kernel<<<(n + 63) / 64, 256>>>(x, W, g_h, n);

    // K2: attention scalars + zero denominators
    {
        const int t = n * HH;
        att_kernel<<<(t + 255) / 256, 256>>>(g_h, att_src, att_dst,
                                             g_asrc, g_adst, g_s, n);
    }

    // K3: softmax denominators
    edge_sum_kernel<<<(ET + 255) / 256, 256>>>(ei, E, n, g_asrc, g_adst, g_s);

    // K4: aggregation
    {
        const long long t = (long long)ET * 16;
        aggregate_kernel<<<(int)((t + 255) / 256), 256>>>(ei, E, n, g_asrc,
                                                          g_adst, g_s, g_h, out);
    }

    // K5: bias + log_softmax
    logsoftmax_kernel<<<(n * 32 + 255) / 256, 256>>>(out, bias, n);
}

// round 16
// speedup vs baseline: 2.6361x; 2.6361x over previous
#include <cuda_runtime.h>
#include <cuda_bf16.h>
#include <cstdint>

// Problem constants (fixed shapes per reference)
#define NN      100000
#define EE      1600000
#define FF      256
#define HH      8
#define CC      8
#define HC      64
#define NEG_SLOPE 0.2f

// ---------------- scratch (device globals; no allocation allowed) ----------
__device__ __align__(16) float g_h[NN * HC];      // projected features [N,64]
__device__ __align__(16) float g_asrc[NN * HH];   // per-node src attention [N,8]
__device__ __align__(16) float g_adst[NN * HH];   // per-node dst attention [N,8]
__device__ int g_is64;                            // edge_index dtype flag
__device__ int g_deg[NN];                         // in-degree histogram
__device__ int g_rowptr[NN];                      // CSR row offsets
__device__ int g_cursor[NN];                      // scatter cursors
__device__ int g_csr[EE];                         // src ids grouped by dst

// ---------------- helpers --------------------------------------------------
__device__ __forceinline__ float lrelu(float v) {
    return v > 0.f ? v : NEG_SLOPE * v;
}

__device__ __forceinline__ void load_edge(const void* eiv, int is64, int E,
                                          int e, int& src, int& dst) {
    if (is64) {
        const long long* p = (const long long*)eiv;
        src = (int)p[e];
        dst = (int)p[(size_t)E + e];
    } else {
        const int* p = (const int*)eiv;
        src = p[e];
        dst = p[E + e];
    }
}

// ---------------- K0: edge_index dtype probe -------------------------------
// int64 values < 2^31 => all odd int32 words are zero (little-endian).
__global__ void detect_kernel(const int* ei) {
    int nz = 0;
#pragma unroll
    for (int i = 0; i < 64; i++) nz |= ei[2 * i + 1];
    g_is64 = (nz == 0) ? 1 : 0;
}

// ---------------- K1: zero the degree histogram ----------------------------
__global__ void zero_deg_kernel(int n) {
    const int i = blockIdx.x * blockDim.x + threadIdx.x;
    if (i < n) g_deg[i] = 0;
}

// ---------------- K2: in-degree histogram (int atomics, not f32 reds) ------
__global__ void hist_kernel(const void* eiv, int E) {
    const int e = blockIdx.x * blockDim.x + threadIdx.x;
    if (e >= E) return;
    int src, dst;
    load_edge(eiv, g_is64, E, e, src, dst);
    atomicAdd(&g_deg[dst], 1);
}

// ---------------- K3: exclusive scan over degrees (single block) -----------
__global__ __launch_bounds__(1024) void scan_kernel(int n) {
    __shared__ int part[1024];
    const int t = threadIdx.x;
    const int chunk = (n + 1023) / 1024;
    const int start = t * chunk;
    const int end   = min(start + chunk, n);

    int sum = 0;
    for (int i = start; i < end; i++) sum += g_deg[i];
    part[t] = sum;
    __syncthreads();

    // Hillis-Steele inclusive scan
    for (int off = 1; off < 1024; off <<= 1) {
        int v = part[t];
        int add = (t >= off) ? part[t - off] : 0;
        __syncthreads();
        part[t] = v + add;
        __syncthreads();
    }

    int prefix = (t == 0) ? 0 : part[t - 1];
    for (int i = start; i < end; i++) {
        g_rowptr[i] = prefix;
        g_cursor[i] = prefix;
        prefix += g_deg[i];
    }
}

// ---------------- K4: scatter src ids into CSR buckets ---------------------
__global__ void scatter_kernel(const void* eiv, int E) {
    const int e = blockIdx.x * blockDim.x + threadIdx.x;
    if (e >= E) return;
    int src, dst;
    load_edge(eiv, g_is64, E, e, src, dst);
    const int pos = atomicAdd(&g_cursor[dst], 1);
    g_csr[pos] = src;
}

// ---------------- K5: GEMM h = x @ W^T  ([N,256]x[64,256]^T -> [N,64]) -----
__global__ __launch_bounds__(256) void gemm_kernel(
    const float* __restrict__ x, const float* __restrict__ W,
    float* __restrict__ h, int n)
{
    __shared__ float sA[64][64];   // [k][row]
    __shared__ float sB[64][64];   // [k][col]

    const int tid = threadIdx.x;
    const int r0  = blockIdx.x * 64;
    const int row = tid & 63;
    const int kb  = (tid >> 6) * 16;
    const int ty  = tid >> 4;
    const int tx  = tid & 15;

    float acc[4][4];
#pragma unroll
    for (int i = 0; i < 4; i++)
#pragma unroll
        for (int j = 0; j < 4; j++) acc[i][j] = 0.f;

    for (int k0 = 0; k0 < FF; k0 += 64) {
        const int gr = r0 + row;
#pragma unroll
        for (int j = 0; j < 4; j++) {
            const int kk = kb + j * 4;
            float4 v = make_float4(0.f, 0.f, 0.f, 0.f);
            if (gr < n)
                v = *(const float4*)&x[(size_t)gr * FF + k0 + kk];
            sA[kk + 0][row] = v.x;
            sA[kk + 1][row] = v.y;
            sA[kk + 2][row] = v.z;
            sA[kk + 3][row] = v.w;
        }
#pragma unroll
        for (int j = 0; j < 4; j++) {
            const int kk = kb + j * 4;
            float4 v = *(const float4*)&W[(size_t)row * FF + k0 + kk];
            sB[kk + 0][row] = v.x;
            sB[kk + 1][row] = v.y;
            sB[kk + 2][row] = v.z;
            sB[kk + 3][row] = v.w;
        }
        __syncthreads();

#pragma unroll 16
        for (int kk = 0; kk < 64; kk++) {
            const float4 a = *(const float4*)&sA[kk][ty * 4];
            const float4 b = *(const float4*)&sB[kk][tx * 4];
            acc[0][0] += a.x * b.x; acc[0][1] += a.x * b.y; acc[0][2] += a.x * b.z; acc[0][3] += a.x * b.w;
            acc[1][0] += a.y * b.x; acc[1][1] += a.y * b.y; acc[1][2] += a.y * b.z; acc[1][3] += a.y * b.w;
            acc[2][0] += a.z * b.x; acc[2][1] += a.z * b.y; acc[2][2] += a.z * b.z; acc[2][3] += a.z * b.w;
            acc[3][0] += a.w * b.x; acc[3][1] += a.w * b.y; acc[3][2] += a.w * b.z; acc[3][3] += a.w * b.w;
        }
        __syncthreads();
    }

#pragma unroll
    for (int i = 0; i < 4; i++) {
        const int gr = r0 + ty * 4 + i;
        if (gr < n) {
            float4 v = make_float4(acc[i][0], acc[i][1], acc[i][2], acc[i][3]);
            *(float4*)&h[(size_t)gr * HC + tx * 4] = v;
        }
    }
}

// ---------------- K6: per-(node,head) attention terms ----------------------
__global__ void att_kernel(const float* __restrict__ h,
                           const float* __restrict__ att_src,
                           const float* __restrict__ att_dst,
                           float* __restrict__ asrc, float* __restrict__ adst,
                           int n)
{
    const int i = blockIdx.x * blockDim.x + threadIdx.x;
    if (i >= n * HH) return;
    const int node = i >> 3;
    const int hd   = i & 7;

    const float4 h0 = *(const float4*)&h[(size_t)node * HC + hd * 8];
    const float4 h1 = *(const float4*)&h[(size_t)node * HC + hd * 8 + 4];
    const float4 s0 = *(const float4*)&att_src[hd * 8];
    const float4 s1 = *(const float4*)&att_src[hd * 8 + 4];
    const float4 d0 = *(const float4*)&att_dst[hd * 8];
    const float4 d1 = *(const float4*)&att_dst[hd * 8 + 4];

    float as = h0.x * s0.x + h0.y * s0.y + h0.z * s0.z + h0.w * s0.w
             + h1.x * s1.x + h1.y * s1.y + h1.z * s1.z + h1.w * s1.w;
    float ad = h0.x * d0.x + h0.y * d0.y + h0.z * d0.z + h0.w * d0.w
             + h1.x * d1.x + h1.y * d1.y + h1.z * d1.z + h1.w * d1.w;

    asrc[i] = as;
    adst[i] = ad;
}

// ---------------- K7: fused gather-aggregate + softmax + log_softmax -------
// One warp per destination node. Lane l owns output columns l and l+32.
// Walks the CSR edge list: computes exp(leaky_relu(logit)) per head locally,
// accumulates numerator and denominator in registers. Zero atomics.
__global__ __launch_bounds__(256) void node_agg_kernel(
    const float* __restrict__ h,
    const float* __restrict__ asrc, const float* __restrict__ adst,
    const float* __restrict__ bias, float* __restrict__ out, int n)
{
    const int warp = (blockIdx.x * blockDim.x + threadIdx.x) >> 5;
    const int lane = threadIdx.x & 31;
    if (warp >= n) return;
    const int v  = warp;
    const int ha = lane >> 3;        // head of column `lane`   (0..3)
    const int hb = ha + 4;           // head of column `lane+32` (4..7)

    const float adst_a = adst[(size_t)v * HH + ha];
    const float adst_b = adst[(size_t)v * HH + hb];

    // self-loop contribution
    float ea = __expf(lrelu(asrc[(size_t)v * HH + ha] + adst_a));
    float eb = __expf(lrelu(asrc[(size_t)v * HH + hb] + adst_b));
    float acc0 = ea * h[(size_t)v * HC + lane];
    float acc1 = eb * h[(size_t)v * HC + 32 + lane];
    float den_a = ea, den_b = eb;

    const int row = g_rowptr[v];
    const int deg = g_deg[v];
    for (int i = 0; i < deg; i++) {
        const int src = g_csr[row + i];
        const float e0 = __expf(lrelu(asrc[(size_t)src * HH + ha] + adst_a));
        const float e1 = __expf(lrelu(asrc[(size_t)src * HH + hb] + adst_b));
        acc0 += e0 * h[(size_t)src * HC + lane];
        acc1 += e1 * h[(size_t)src * HC + 32 + lane];
        den_a += e0;
        den_b += e1;
    }

    float v0 = acc0 / (den_a + 1e-16f) + bias[lane];
    float v1 = acc1 / (den_b + 1e-16f) + bias[32 + lane];

    // log_softmax across the 64 columns
    float m = fmaxf(v0, v1);
#pragma unroll
    for (int o = 16; o > 0; o >>= 1)
        m = fmaxf(m, __shfl_xor_sync(0xFFFFFFFFu, m, o));

    float sum = __expf(v0 - m) + __expf(v1 - m);
#pragma unroll
    for (int o = 16; o > 0; o >>= 1)
        sum += __shfl_xor_sync(0xFFFFFFFFu, sum, o);

    const float lse = m + __logf(sum);
    out[(size_t)v * HC + lane]      = v0 - lse;
    out[(size_t)v * HC + 32 + lane] = v1 - lse;
}

// ---------------- launch ---------------------------------------------------
extern "C" void kernel_launch(void* const* d_in, const int* in_sizes, int n_in,
                              void* d_out, int out_size)
{
    const float* x        = (const float*)d_in[0];
    const void*  ei       = d_in[1];                 // int32 OR int64, probed
    const float* W        = (const float*)d_in[2];
    const float* att_src  = (const float*)d_in[3];
    const float* att_dst  = (const float*)d_in[4];
    const float* bias     = (const float*)d_in[5];
    float*       out      = (float*)d_out;

    const int n = in_sizes[0] / FF;       // 100000
    const int E = in_sizes[1] / 2;        // 1600000

    // dtype probe
    detect_kernel<<<1, 1>>>((const int*)ei);

    // CSR build: zero -> histogram -> scan -> scatter
    zero_deg_kernel<<<(n + 255) / 256, 256>>>(n);
    hist_kernel<<<(E + 255) / 256, 256>>>(ei, E);
    scan_kernel<<<1, 1024>>>(n);
    scatter_kernel<<<(E + 255) / 256, 256>>>(ei, E);

    // projection + attention scalars
    gemm_kernel<<<(n + 63) / 64, 256>>>(x, W, g_h, n);
    att_kernel<<<(n * HH + 255) / 256, 256>>>(g_h, att_src, att_dst,
                                              g_asrc, g_adst, n);

    // fused gather-aggregate + softmax + bias + log_softmax (no atomics)
    node_agg_kernel<<<(n * 32 + 255) / 256, 256>>>(g_h, g_asrc, g_adst,
                                                   bias, out, n);
}